// round 11
// baseline (speedup 1.0000x reference)
#include <cuda_runtime.h>
#include <cuda_fp16.h>

#define B_ 64
#define T_ 1024
#define C_ 2
#define N_ 128

__global__ void __launch_bounds__(256, 1)
crf_fwd_kernel(const float* __restrict__ emissions,   // [B,T,C,N]
               const int*   __restrict__ lengths,     // [B]
               const float* __restrict__ trans,       // [1,C,N,N]
               const float* __restrict__ start_t,     // [1,C,N]
               const float* __restrict__ end_t,       // [1,C,N]
               float*       __restrict__ out)         // [B,C]
{
    const int tid = threadIdx.x;
    const int h   = tid & 1;            // K-half this thread sums (rows h*64..h*64+63)
    const int j   = tid >> 1;           // tag column this thread serves
    const int wid = tid >> 5;
    const int bc  = blockIdx.x;         // chain id
    const int b   = bc >> 1;
    const int c   = bc & 1;
    const int len = lengths[b];         // in [T/2, T]

    __shared__ __align__(16) __half r_h[2][N_];   // scaled forward vector, fp16
    __shared__ __align__(16) float red_sh[8];

    // ---- E packed fp16, this thread's half: e2h[m] = rows (h*64+2m, h*64+2m+1) of col j ----
    __half2 e2h[32];
    {
        const float* tb = trans + (size_t)c * N_ * N_ + (size_t)(h * 64) * N_ + j;
#pragma unroll
        for (int m = 0; m < 32; ++m) {
            float lo = __expf(tb[(size_t)(2 * m) * N_]);
            float hi = __expf(tb[(size_t)(2 * m + 1) * N_]);
            e2h[m] = __floats2half2_rn(lo, hi);
        }
    }

    const float* ebase = emissions + ((size_t)b * T_ * C_ + c) * N_ + j;
    const int estride = C_ * N_;

    // ---- init (h=0 lanes own the column state) ----
    if (h == 0)
        r_h[0][j] = __float2half_rn(__expf(start_t[c * N_ + j] + ebase[0]));
    int kacc = 0;                       // sum of fp16 biased exponents of cn
    __syncthreads();

    // ---- RAW emission ring (h=0 only), depth 8; slot (t & 7) holds raw emit_t ----
    float ering[8];
    if (h == 0) {
#pragma unroll
        for (int d = 1; d <= 8; ++d) {
            int tt = d; tt = (tt > T_ - 1) ? (T_ - 1) : tt;
            ering[d & 7] = __ldg(ebase + (size_t)tt * estride);
        }
    }

    // ---- main scan, clamp-free: refills reach t+15 <= len-1 <= T-1 ----
    int t = 1;
#pragma unroll 1
    for (; t + 15 < len; t += 8) {      // t stays ≡ 1 (mod 8)
#pragma unroll
        for (int u = 0; u < 8; ++u) {
            const int cur  = (1 + u) & 1;   // compile-time buffer parity
            const int prv  = cur ^ 1;
            const int slot = (1 + u) & 7;   // compile-time ring slot
            const int tq   = t + u;

            float em = 0.f, inv = 0.f;
            if (h == 0) {
                // pow-2 normalizer from previous step's r[0] (fp16 exponent bits)
                unsigned short ub = __half_as_ushort(r_h[prv][0]);
                int ke = (ub >> 10) & 0x1f;
                inv = __int_as_float((131 - ke) << 23);   // 2^(4-ke), exact
                kacc += ke;
                // emission: exp of an 8-step-old raw value; refill 8 ahead (raw)
                em = __expf(ering[slot]);
                ering[slot] = __ldg(ebase + (size_t)(tq + 8) * estride);
            }

            // ---- half-dot: rows h*64..h*64+63 of column j ----
            const uint4* pv = reinterpret_cast<const uint4*>(&r_h[prv][h * 64]);
            __half2 a0 = __float2half2_rn(0.f), a1 = a0, a2 = a0, a3 = a0;
#pragma unroll
            for (int k = 0; k < 8; ++k) {   // 8 x LDS.128 = 64 rows
                uint4 v = pv[k];
                a0 = __hfma2(e2h[4 * k + 0], *reinterpret_cast<const __half2*>(&v.x), a0);
                a1 = __hfma2(e2h[4 * k + 1], *reinterpret_cast<const __half2*>(&v.y), a1);
                a2 = __hfma2(e2h[4 * k + 2], *reinterpret_cast<const __half2*>(&v.z), a2);
                a3 = __hfma2(e2h[4 * k + 3], *reinterpret_cast<const __half2*>(&v.w), a3);
            }
            float s0 = __low2float(a0) + __high2float(a0);
            float s1 = __low2float(a1) + __high2float(a1);
            float S  = ((s0 + s1) + (__low2float(a2) + __high2float(a2)))
                       + (__low2float(a3) + __high2float(a3));
            // combine the two K-halves: partner lane differs only in bit 0
            S += __shfl_xor_sync(0xffffffffu, S, 1);

            if (h == 0)
                r_h[cur][j] = __float2half_rn(S * (em * inv));
            __syncthreads();
        }
    }
    // tail (≤ 15 steps), runtime parity, clamped refills
#pragma unroll 1
    for (; t < len; ++t) {
        const int cur = t & 1;
        const int prv = cur ^ 1;
        float em = 0.f, inv = 0.f;
        if (h == 0) {
            unsigned short ub = __half_as_ushort(r_h[prv][0]);
            int ke = (ub >> 10) & 0x1f;
            inv = __int_as_float((131 - ke) << 23);
            kacc += ke;
            em = __expf(ering[t & 7]);
            int tt = t + 8; tt = (tt > T_ - 1) ? (T_ - 1) : tt;
            ering[t & 7] = __ldg(ebase + (size_t)tt * estride);
        }
        const uint4* pv = reinterpret_cast<const uint4*>(&r_h[prv][h * 64]);
        __half2 a0 = __float2half2_rn(0.f), a1 = a0, a2 = a0, a3 = a0;
#pragma unroll
        for (int k = 0; k < 8; ++k) {
            uint4 v = pv[k];
            a0 = __hfma2(e2h[4 * k + 0], *reinterpret_cast<const __half2*>(&v.x), a0);
            a1 = __hfma2(e2h[4 * k + 1], *reinterpret_cast<const __half2*>(&v.y), a1);
            a2 = __hfma2(e2h[4 * k + 2], *reinterpret_cast<const __half2*>(&v.z), a2);
            a3 = __hfma2(e2h[4 * k + 3], *reinterpret_cast<const __half2*>(&v.w), a3);
        }
        float s0 = __low2float(a0) + __high2float(a0);
        float s1 = __low2float(a1) + __high2float(a1);
        float S  = ((s0 + s1) + (__low2float(a2) + __high2float(a2)))
                   + (__low2float(a3) + __high2float(a3));
        S += __shfl_xor_sync(0xffffffffu, S, 1);
        if (h == 0)
            r_h[cur][j] = __float2half_rn(S * (em * inv));
        __syncthreads();
    }

    // ---- finalize: logZ = (kacc - 4*(len-1))*ln2 + log( sum_j r_j e^{end_j} ) ----
    float v = 0.f;
    if (h == 0)
        v = __half2float(r_h[(len - 1) & 1][j]) * __expf(end_t[c * N_ + j]);
#pragma unroll
    for (int o = 16; o > 0; o >>= 1)
        v += __shfl_xor_sync(0xffffffffu, v, o);
    if ((tid & 31) == 0) red_sh[wid] = v;
    __syncthreads();
    if (tid == 0) {
        float Sf = 0.f;
#pragma unroll
        for (int w = 0; w < 8; ++w) Sf += red_sh[w];
        float logK = (float)(kacc - 4 * (len - 1)) * 0.6931471805599453f;
        out[bc] = logK + logf(Sf);
    }
}

extern "C" void kernel_launch(void* const* d_in, const int* in_sizes, int n_in,
                              void* d_out, int out_size) {
    // Identify inputs by element count (robust to metadata ordering).
    const float* emissions = nullptr;
    const int*   lengths   = nullptr;
    const float* trans     = nullptr;
    const float* start_t   = nullptr;
    const float* end_t     = nullptr;

    for (int i = 0; i < n_in; ++i) {
        int sz = in_sizes[i];
        if (sz == B_ * T_ * C_ * N_)      emissions = (const float*)d_in[i];
        else if (sz == B_)                lengths   = (const int*)d_in[i];
        else if (sz == C_ * N_ * N_)      trans     = (const float*)d_in[i];
    }
    if (n_in > 3 && in_sizes[3] == C_ * N_) start_t = (const float*)d_in[3];
    for (int i = 0; i < n_in; ++i) {
        if (in_sizes[i] == C_ * N_ && (const float*)d_in[i] != start_t)
            end_t = (const float*)d_in[i];
    }
    if (!start_t) {
        for (int i = 0; i < n_in; ++i)
            if (in_sizes[i] == C_ * N_) { start_t = (const float*)d_in[i]; break; }
        for (int i = 0; i < n_in; ++i)
            if (in_sizes[i] == C_ * N_ && (const float*)d_in[i] != start_t)
                end_t = (const float*)d_in[i];
    }

    float* out = (float*)d_out;
    crf_fwd_kernel<<<B_ * C_, 256>>>(emissions, lengths, trans, start_t, end_t, out);
}

// round 12
// speedup vs baseline: 1.7790x; 1.7790x over previous
#include <cuda_runtime.h>
#include <cuda_fp16.h>

#define B_ 64
#define T_ 1024
#define C_ 2
#define N_ 128

// fp16 dot over ALL 128 rows, fp16 epilogue: returns half2 with the total in
// BOTH halves. e2h[m] packs rows (2m, 2m+1) of E column j.
__device__ __forceinline__ __half2 dot128_h16(const __half* rbuf, const __half2* e2h) {
    const uint4* pv = reinterpret_cast<const uint4*>(rbuf);
    __half2 a0 = __float2half2_rn(0.f), a1 = a0, a2 = a0, a3 = a0;
#pragma unroll
    for (int k = 0; k < 16; ++k) {       // 16 x LDS.128 = 128 rows
        uint4 v = pv[k];
        a0 = __hfma2(e2h[4 * k + 0], *reinterpret_cast<const __half2*>(&v.x), a0);
        a1 = __hfma2(e2h[4 * k + 1], *reinterpret_cast<const __half2*>(&v.y), a1);
        a2 = __hfma2(e2h[4 * k + 2], *reinterpret_cast<const __half2*>(&v.z), a2);
        a3 = __hfma2(e2h[4 * k + 3], *reinterpret_cast<const __half2*>(&v.w), a3);
    }
    __half2 A = __hadd2(a0, a1);
    __half2 Bb = __hadd2(a2, a3);
    __half2 Cc = __hadd2(A, Bb);                 // (sum_even, sum_odd)
    return __hadd2(Cc, __lowhigh2highlow(Cc));   // total in both halves
}

__global__ void __launch_bounds__(128, 1)
crf_fwd_kernel(const float* __restrict__ emissions,   // [B,T,C,N]
               const int*   __restrict__ lengths,     // [B]
               const float* __restrict__ trans,       // [1,C,N,N]
               const float* __restrict__ start_t,     // [1,C,N]
               const float* __restrict__ end_t,       // [1,C,N]
               float*       __restrict__ out)         // [B,C]
{
    const int j   = threadIdx.x;        // tag column this thread owns
    const int bc  = blockIdx.x;         // chain id
    const int b   = bc >> 1;
    const int c   = bc & 1;
    const int wid = j >> 5;
    const int len = lengths[b];         // in [T/2, T]

    __shared__ __align__(16) __half r_h[2][N_];   // scaled forward vector, fp16
    __shared__ __align__(16) float red_sh[4];

    // ---- E packed fp16: e2h[m] = (exp(trans[c,2m,j]), exp(trans[c,2m+1,j])) ----
    __half2 e2h[64];
    {
        const float* tb = trans + (size_t)c * N_ * N_ + j;
#pragma unroll
        for (int m = 0; m < 64; ++m) {
            float lo = __expf(tb[(size_t)(2 * m) * N_]);
            float hi = __expf(tb[(size_t)(2 * m + 1) * N_]);
            e2h[m] = __floats2half2_rn(lo, hi);
        }
    }

    const float* ebase = emissions + ((size_t)b * T_ * C_ + c) * N_ + j;
    const int estride = C_ * N_;

    // ---- init: r_0 = exp(start + emit_0)  (|.| in [e^-6, e^6] -> fp16 ok) ----
    r_h[0][j] = __float2half_rn(__expf(start_t[c * N_ + j] + ebase[0]));
    int kacc = 0;                       // sum of fp16 biased exponents of cn
    __syncthreads();

    // ---- RAW emission ring, depth 8; slot (t & 7) holds raw emit_t.
    //      __expf applied only at consumption (8 steps after the load). ----
    float ering[8];
#pragma unroll
    for (int d = 1; d <= 8; ++d) {
        int tt = d; tt = (tt > T_ - 1) ? (T_ - 1) : tt;
        ering[d & 7] = __ldg(ebase + (size_t)tt * estride);
    }

    // ---- main scan, clamp-free: refills reach t+15 <= len-1 <= T-1 ----
    // Normalization: inv = 2^(4-ke), ke = biased fp16 exponent of r_prev[0];
    // exact bookkeeping logK = (kacc - 4*(len-1)) * ln2.
    int t = 1;
#pragma unroll 1
    for (; t + 15 < len; t += 8) {      // t stays ≡ 1 (mod 8)
#pragma unroll
        for (int u = 0; u < 8; ++u) {
            const int cur  = (1 + u) & 1;   // compile-time buffer parity
            const int prv  = cur ^ 1;
            const int slot = (1 + u) & 7;   // compile-time ring slot
            const int tq   = t + u;

            // pow-2 normalizer from previous step's r[0] (fp16 exponent bits)
            unsigned short ub = __half_as_ushort(r_h[prv][0]);
            int   ke  = (ub >> 10) & 0x1f;
            float inv = __int_as_float((131 - ke) << 23);   // 2^(4-ke), exact
            kacc += ke;

            // emission: exp of an 8-step-old raw value; refill 8 ahead (raw).
            // g = em * inv converted to half2 EARLY (off the dot's critical path).
            float em = __expf(ering[slot]);
            ering[slot] = __ldg(ebase + (size_t)(tq + 8) * estride);
            __half2 g2 = __float2half2_rn(em * inv);

            __half2 S2 = dot128_h16(r_h[prv], e2h);
            r_h[cur][j] = __low2half(__hmul2(S2, g2));
            __syncthreads();
        }
    }
    // tail (≤ 15 steps), runtime parity, clamped refills
#pragma unroll 1
    for (; t < len; ++t) {
        const int cur = t & 1;
        const int prv = cur ^ 1;
        unsigned short ub = __half_as_ushort(r_h[prv][0]);
        int   ke  = (ub >> 10) & 0x1f;
        float inv = __int_as_float((131 - ke) << 23);
        kacc += ke;
        float em = __expf(ering[t & 7]);
        int tt = t + 8; tt = (tt > T_ - 1) ? (T_ - 1) : tt;
        ering[t & 7] = __ldg(ebase + (size_t)tt * estride);
        __half2 g2 = __float2half2_rn(em * inv);
        __half2 S2 = dot128_h16(r_h[prv], e2h);
        r_h[cur][j] = __low2half(__hmul2(S2, g2));
        __syncthreads();
    }

    // ---- finalize: logZ = (kacc - 4*(len-1))*ln2 + log( sum_j r_j e^{end_j} ) ----
    float v = __half2float(r_h[(len - 1) & 1][j]) * __expf(end_t[c * N_ + j]);
    float s = v;
#pragma unroll
    for (int o = 16; o > 0; o >>= 1)
        s += __shfl_xor_sync(0xffffffffu, s, o);
    if ((j & 31) == 0) red_sh[wid] = s;
    __syncthreads();
    if (j == 0) {
        float Sf = (red_sh[0] + red_sh[1]) + (red_sh[2] + red_sh[3]);
        float logK = (float)(kacc - 4 * (len - 1)) * 0.6931471805599453f;
        out[bc] = logK + logf(Sf);
    }
}

extern "C" void kernel_launch(void* const* d_in, const int* in_sizes, int n_in,
                              void* d_out, int out_size) {
    // Identify inputs by element count (robust to metadata ordering).
    const float* emissions = nullptr;
    const int*   lengths   = nullptr;
    const float* trans     = nullptr;
    const float* start_t   = nullptr;
    const float* end_t     = nullptr;

    for (int i = 0; i < n_in; ++i) {
        int sz = in_sizes[i];
        if (sz == B_ * T_ * C_ * N_)      emissions = (const float*)d_in[i];
        else if (sz == B_)                lengths   = (const int*)d_in[i];
        else if (sz == C_ * N_ * N_)      trans     = (const float*)d_in[i];
    }
    if (n_in > 3 && in_sizes[3] == C_ * N_) start_t = (const float*)d_in[3];
    for (int i = 0; i < n_in; ++i) {
        if (in_sizes[i] == C_ * N_ && (const float*)d_in[i] != start_t)
            end_t = (const float*)d_in[i];
    }
    if (!start_t) {
        for (int i = 0; i < n_in; ++i)
            if (in_sizes[i] == C_ * N_) { start_t = (const float*)d_in[i]; break; }
        for (int i = 0; i < n_in; ++i)
            if (in_sizes[i] == C_ * N_ && (const float*)d_in[i] != start_t)
                end_t = (const float*)d_in[i];
    }

    float* out = (float*)d_out;
    crf_fwd_kernel<<<B_ * C_, N_>>>(emissions, lengths, trans, start_t, end_t, out);
}

// round 13
// speedup vs baseline: 2.2375x; 1.2577x over previous
#include <cuda_runtime.h>
#include <cuda_fp16.h>

#define B_ 64
#define T_ 1024
#define C_ 2
#define N_ 128

// Scratch (static __device__: allowed; no dynamic allocation).
__device__ float g_af[B_ * C_ * N_];   // alpha_hat_m  (forward, normalized)
__device__ float g_bt[B_ * C_ * N_];   // beta_tilde_m (backward, normalized, * em_m)
__device__ int   g_kf[B_ * C_];
__device__ int   g_kb[B_ * C_];

// fp16 dot over 128 elements, fp16 epilogue: total in BOTH halves of result.
__device__ __forceinline__ __half2 dot128_h16(const __half* rbuf, const __half2* e2h) {
    const uint4* pv = reinterpret_cast<const uint4*>(rbuf);
    __half2 a0 = __float2half2_rn(0.f), a1 = a0, a2 = a0, a3 = a0;
#pragma unroll
    for (int k = 0; k < 16; ++k) {
        uint4 v = pv[k];
        a0 = __hfma2(e2h[4 * k + 0], *reinterpret_cast<const __half2*>(&v.x), a0);
        a1 = __hfma2(e2h[4 * k + 1], *reinterpret_cast<const __half2*>(&v.y), a1);
        a2 = __hfma2(e2h[4 * k + 2], *reinterpret_cast<const __half2*>(&v.z), a2);
        a3 = __hfma2(e2h[4 * k + 3], *reinterpret_cast<const __half2*>(&v.w), a3);
    }
    __half2 A  = __hadd2(a0, a1);
    __half2 Bb = __hadd2(a2, a3);
    __half2 Cc = __hadd2(A, Bb);
    return __hadd2(Cc, __lowhigh2highlow(Cc));
}

// grid 256: blockIdx < 128 -> forward chain bc=blockIdx; else backward chain bc-128.
__global__ void __launch_bounds__(128, 1)
crf_bidir_kernel(const float* __restrict__ emissions,   // [B,T,C,N]
                 const int*   __restrict__ lengths,     // [B]
                 const float* __restrict__ trans,       // [1,C,N,N]
                 const float* __restrict__ start_t,     // [1,C,N]
                 const float* __restrict__ end_t)       // [1,C,N]
{
    const int j    = threadIdx.x;
    const int role = blockIdx.x >> 7;     // 0 = forward, 1 = backward
    const int bc   = blockIdx.x & 127;
    const int b    = bc >> 1;
    const int c    = bc & 1;
    const int len  = lengths[b];          // in [T/2, T]
    const int m    = (len - 1) >> 1;      // meeting point

    __shared__ __align__(16) __half r_h[2][N_];

    const float* ebase = emissions + ((size_t)b * T_ * C_ + c) * N_ + j;
    const int estride = C_ * N_;
    int kacc = 0;
    float ering[8];

    if (role == 0) {
        // ---------------- FORWARD: steps t = 1..m ----------------
        __half2 e2h[64];   // (E[2q,j], E[2q+1,j]) : column j of E
        {
            const float* tb = trans + (size_t)c * N_ * N_ + j;
#pragma unroll
            for (int q = 0; q < 64; ++q) {
                float lo = __expf(tb[(size_t)(2 * q) * N_]);
                float hi = __expf(tb[(size_t)(2 * q + 1) * N_]);
                e2h[q] = __floats2half2_rn(lo, hi);
            }
        }
        r_h[0][j] = __float2half_rn(__expf(start_t[c * N_ + j] + ebase[0]));
        __syncthreads();
#pragma unroll
        for (int d = 1; d <= 8; ++d)
            ering[d & 7] = __ldg(ebase + (size_t)d * estride);

        const int fend = m + 1;
        int t = 1;
#pragma unroll 1
        for (; t + 7 < fend; t += 8) {
#pragma unroll
            for (int u = 0; u < 8; ++u) {
                const int cur  = (1 + u) & 1;
                const int prv  = cur ^ 1;
                const int slot = (1 + u) & 7;
                unsigned short ub = __half_as_ushort(r_h[prv][0]);
                int   ke  = (ub >> 10) & 0x1f;
                float inv = __int_as_float((131 - ke) << 23);
                kacc += ke;
                float em = __expf(ering[slot]);
                int tt = t + u + 8; tt = (tt > T_ - 1) ? (T_ - 1) : tt;
                ering[slot] = __ldg(ebase + (size_t)tt * estride);
                __half2 g2 = __float2half2_rn(em * inv);
                __half2 S2 = dot128_h16(r_h[prv], e2h);
                r_h[cur][j] = __low2half(__hmul2(S2, g2));
                __syncthreads();
            }
        }
#pragma unroll 1
        for (; t < fend; ++t) {
            const int cur = t & 1;
            const int prv = cur ^ 1;
            unsigned short ub = __half_as_ushort(r_h[prv][0]);
            int   ke  = (ub >> 10) & 0x1f;
            float inv = __int_as_float((131 - ke) << 23);
            kacc += ke;
            float em = __expf(ering[t & 7]);
            int tt = t + 8; tt = (tt > T_ - 1) ? (T_ - 1) : tt;
            ering[t & 7] = __ldg(ebase + (size_t)tt * estride);
            __half2 g2 = __float2half2_rn(em * inv);
            __half2 S2 = dot128_h16(r_h[prv], e2h);
            r_h[cur][j] = __low2half(__hmul2(S2, g2));
            __syncthreads();
        }
        g_af[bc * N_ + j] = __half2float(r_h[m & 1][j]);
        if (j == 0) g_kf[bc] = kacc;
    } else {
        // ---------------- BACKWARD: nb = len-1-m steps ----------------
        // State pre-multiplied: bt[tau][i] = beta_tau_i * em_tau_i.
        // Step: beta_{tau-1,i} = sum_j E[i][j]*bt[tau][j];
        //       bt[tau-1][i] = beta_{tau-1,i} * em_{tau-1,i} * inv.
        __half2 e2h[64];   // (E[j,2q], E[j,2q+1]) : row j of E (contiguous)
        {
            const float2* tb2 = reinterpret_cast<const float2*>(
                trans + (size_t)c * N_ * N_ + (size_t)j * N_);
#pragma unroll
            for (int q = 0; q < 64; ++q) {
                float2 w = tb2[q];
                e2h[q] = __floats2half2_rn(__expf(w.x), __expf(w.y));
            }
        }
        const int tau0 = len - 1;
        const int nb   = len - 1 - m;
        r_h[0][j] = __float2half_rn(__expf(end_t[c * N_ + j] +
                                           ebase[(size_t)tau0 * estride]));
        __syncthreads();
#pragma unroll
        for (int s0 = 0; s0 < 8; ++s0) {
            int tt = tau0 - 1 - s0; tt = (tt < 0) ? 0 : tt;
            ering[s0] = __ldg(ebase + (size_t)tt * estride);
        }
        int s = 0;
#pragma unroll 1
        for (; s + 7 < nb; s += 8) {
#pragma unroll
            for (int u = 0; u < 8; ++u) {
                const int prv = u & 1;      // s is a multiple of 8
                const int cur = prv ^ 1;
                unsigned short ub = __half_as_ushort(r_h[prv][0]);
                int   ke  = (ub >> 10) & 0x1f;
                float inv = __int_as_float((131 - ke) << 23);
                kacc += ke;
                float em = __expf(ering[(s + u) & 7]);      // emit_{tau0-1-(s+u)}
                int tt = tau0 - 9 - (s + u); tt = (tt < 0) ? 0 : tt;
                ering[(s + u) & 7] = __ldg(ebase + (size_t)tt * estride);
                __half2 g2 = __float2half2_rn(em * inv);
                __half2 S2 = dot128_h16(r_h[prv], e2h);
                r_h[cur][j] = __low2half(__hmul2(S2, g2));
                __syncthreads();
            }
        }
#pragma unroll 1
        for (; s < nb; ++s) {
            const int prv = s & 1;
            const int cur = prv ^ 1;
            unsigned short ub = __half_as_ushort(r_h[prv][0]);
            int   ke  = (ub >> 10) & 0x1f;
            float inv = __int_as_float((131 - ke) << 23);
            kacc += ke;
            float em = __expf(ering[s & 7]);
            int tt = tau0 - 9 - s; tt = (tt < 0) ? 0 : tt;
            ering[s & 7] = __ldg(ebase + (size_t)tt * estride);
            __half2 g2 = __float2half2_rn(em * inv);
            __half2 S2 = dot128_h16(r_h[prv], e2h);
            r_h[cur][j] = __low2half(__hmul2(S2, g2));
            __syncthreads();
        }
        g_bt[bc * N_ + j] = __half2float(r_h[nb & 1][j]);
        if (j == 0) g_kb[bc] = kacc;
    }
}

// logZ = (kf + kb - 4*(len-1))*ln2 + log( sum_j af_j * bt_j * e^{-emit_m_j} )
__global__ void __launch_bounds__(128, 1)
crf_reduce_kernel(const float* __restrict__ emissions,
                  const int*   __restrict__ lengths,
                  float*       __restrict__ out)
{
    const int j  = threadIdx.x;
    const int bc = blockIdx.x;
    const int b  = bc >> 1;
    const int c  = bc & 1;
    const int len = lengths[b];
    const int m   = (len - 1) >> 1;

    __shared__ float red_sh[4];
    float em_m = emissions[(((size_t)b * T_ + m) * C_ + c) * N_ + j];
    float v = g_af[bc * N_ + j] * g_bt[bc * N_ + j] * __expf(-em_m);
#pragma unroll
    for (int o = 16; o > 0; o >>= 1)
        v += __shfl_xor_sync(0xffffffffu, v, o);
    if ((j & 31) == 0) red_sh[j >> 5] = v;
    __syncthreads();
    if (j == 0) {
        float Sf = (red_sh[0] + red_sh[1]) + (red_sh[2] + red_sh[3]);
        float logK = (float)(g_kf[bc] + g_kb[bc] - 4 * (len - 1)) * 0.6931471805599453f;
        out[bc] = logK + logf(Sf);
    }
}

extern "C" void kernel_launch(void* const* d_in, const int* in_sizes, int n_in,
                              void* d_out, int out_size) {
    const float* emissions = nullptr;
    const int*   lengths   = nullptr;
    const float* trans     = nullptr;
    const float* start_t   = nullptr;
    const float* end_t     = nullptr;

    for (int i = 0; i < n_in; ++i) {
        int sz = in_sizes[i];
        if (sz == B_ * T_ * C_ * N_)      emissions = (const float*)d_in[i];
        else if (sz == B_)                lengths   = (const int*)d_in[i];
        else if (sz == C_ * N_ * N_)      trans     = (const float*)d_in[i];
    }
    if (n_in > 3 && in_sizes[3] == C_ * N_) start_t = (const float*)d_in[3];
    for (int i = 0; i < n_in; ++i) {
        if (in_sizes[i] == C_ * N_ && (const float*)d_in[i] != start_t)
            end_t = (const float*)d_in[i];
    }
    if (!start_t) {
        for (int i = 0; i < n_in; ++i)
            if (in_sizes[i] == C_ * N_) { start_t = (const float*)d_in[i]; break; }
        for (int i = 0; i < n_in; ++i)
            if (in_sizes[i] == C_ * N_ && (const float*)d_in[i] != start_t)
                end_t = (const float*)d_in[i];
    }

    float* out = (float*)d_out;
    crf_bidir_kernel<<<2 * B_ * C_, N_>>>(emissions, lengths, trans, start_t, end_t);
    crf_reduce_kernel<<<B_ * C_, N_>>>(emissions, lengths, out);
}

// round 14
// speedup vs baseline: 2.3759x; 1.0619x over previous
#include <cuda_runtime.h>
#include <cuda_fp16.h>

#define B_ 64
#define T_ 1024
#define C_ 2
#define N_ 128

// Scratch (static __device__: allowed; no dynamic allocation).
__device__ float g_af[B_ * C_ * N_];   // alpha_hat_m  (forward, normalized)
__device__ float g_bt[B_ * C_ * N_];   // beta_tilde_m (backward, normalized, * em)
__device__ int   g_kf[B_ * C_];
__device__ int   g_kb[B_ * C_];
__device__ int   g_assign[2 * B_ * C_]; // bid -> work item (role*128 + bc)

// ---- scheduler: rank 256 half-chain items by step count, map to bids so the
// longest 40 get solo SMs (bids 108..147) and the rest pair long-with-short
// on doubled SMs (bid k with bid k+148 share an SM: LUT_classic[bid % 148]).
__global__ void __launch_bounds__(256, 1)
crf_sched_kernel(const int* __restrict__ lengths) {
    __shared__ int sl[B_];
    int i = threadIdx.x;                 // work item 0..255
    if (i < B_) sl[i] = lengths[i];
    __syncthreads();

    int bc   = i & 127;
    int role = i >> 7;
    int len  = sl[bc >> 1];
    int m    = (len - 1) >> 1;
    int steps = role ? (len - 1 - m) : m;

    int rank = 0;
    for (int k = 0; k < 256; ++k) {
        int lk = sl[(k & 127) >> 1];
        int mk = (lk - 1) >> 1;
        int sk = (k >> 7) ? (lk - 1 - mk) : mk;
        rank += (sk > steps) || (sk == steps && k < i);
    }
    int bid;
    if (rank < 40)        bid = 108 + rank;        // longest 40: solo SMs
    else if (rank < 148)  bid = rank - 40;         // first slot of doubled SMs
    else                  bid = 148 + (255 - rank);// second slot, reversed pairing
    g_assign[bid] = i;
}

// fp16 dot over 128 elements, fp16 epilogue: total in BOTH halves of result.
__device__ __forceinline__ __half2 dot128_h16(const __half* rbuf, const __half2* e2h) {
    const uint4* pv = reinterpret_cast<const uint4*>(rbuf);
    __half2 a0 = __float2half2_rn(0.f), a1 = a0, a2 = a0, a3 = a0;
#pragma unroll
    for (int k = 0; k < 16; ++k) {
        uint4 v = pv[k];
        a0 = __hfma2(e2h[4 * k + 0], *reinterpret_cast<const __half2*>(&v.x), a0);
        a1 = __hfma2(e2h[4 * k + 1], *reinterpret_cast<const __half2*>(&v.y), a1);
        a2 = __hfma2(e2h[4 * k + 2], *reinterpret_cast<const __half2*>(&v.z), a2);
        a3 = __hfma2(e2h[4 * k + 3], *reinterpret_cast<const __half2*>(&v.w), a3);
    }
    __half2 A  = __hadd2(a0, a1);
    __half2 Bb = __hadd2(a2, a3);
    __half2 Cc = __hadd2(A, Bb);
    return __hadd2(Cc, __lowhigh2highlow(Cc));
}

__global__ void __launch_bounds__(128, 2)
crf_bidir_kernel(const float* __restrict__ emissions,   // [B,T,C,N]
                 const int*   __restrict__ lengths,     // [B]
                 const float* __restrict__ trans,       // [1,C,N,N]
                 const float* __restrict__ start_t,     // [1,C,N]
                 const float* __restrict__ end_t)       // [1,C,N]
{
    const int j    = threadIdx.x;
    const int item = g_assign[blockIdx.x];
    const int role = item >> 7;           // 0 = forward, 1 = backward
    const int bc   = item & 127;
    const int b    = bc >> 1;
    const int c    = bc & 1;
    const int len  = lengths[b];          // in [T/2, T]
    const int m    = (len - 1) >> 1;      // meeting point

    __shared__ __align__(16) __half r_h[2][N_];

    const float* ebase = emissions + ((size_t)b * T_ * C_ + c) * N_ + j;
    const int estride = C_ * N_;
    int kacc = 0;
    float ering[8];

    if (role == 0) {
        // ---------------- FORWARD: steps t = 1..m ----------------
        __half2 e2h[64];   // (E[2q,j], E[2q+1,j]) : column j of E
        {
            const float* tb = trans + (size_t)c * N_ * N_ + j;
#pragma unroll
            for (int q = 0; q < 64; ++q) {
                float lo = __expf(tb[(size_t)(2 * q) * N_]);
                float hi = __expf(tb[(size_t)(2 * q + 1) * N_]);
                e2h[q] = __floats2half2_rn(lo, hi);
            }
        }
        r_h[0][j] = __float2half_rn(__expf(start_t[c * N_ + j] + ebase[0]));
        __syncthreads();
#pragma unroll
        for (int d = 1; d <= 8; ++d)
            ering[d & 7] = __ldg(ebase + (size_t)d * estride);

        const int fend = m + 1;
        int t = 1;
#pragma unroll 1
        for (; t + 7 < fend; t += 8) {
#pragma unroll
            for (int u = 0; u < 8; ++u) {
                const int cur  = (1 + u) & 1;
                const int prv  = cur ^ 1;
                const int slot = (1 + u) & 7;
                unsigned short ub = __half_as_ushort(r_h[prv][0]);
                int   ke  = (ub >> 10) & 0x1f;
                float inv = __int_as_float((131 - ke) << 23);   // 2^(4-ke)
                kacc += ke;
                float em = __expf(ering[slot]);
                int tt = t + u + 8; tt = (tt > T_ - 1) ? (T_ - 1) : tt;
                ering[slot] = __ldg(ebase + (size_t)tt * estride);
                __half2 g2 = __float2half2_rn(em * inv);
                __half2 S2 = dot128_h16(r_h[prv], e2h);
                r_h[cur][j] = __low2half(__hmul2(S2, g2));
                __syncthreads();
            }
        }
#pragma unroll 1
        for (; t < fend; ++t) {
            const int cur = t & 1;
            const int prv = cur ^ 1;
            unsigned short ub = __half_as_ushort(r_h[prv][0]);
            int   ke  = (ub >> 10) & 0x1f;
            float inv = __int_as_float((131 - ke) << 23);
            kacc += ke;
            float em = __expf(ering[t & 7]);
            int tt = t + 8; tt = (tt > T_ - 1) ? (T_ - 1) : tt;
            ering[t & 7] = __ldg(ebase + (size_t)tt * estride);
            __half2 g2 = __float2half2_rn(em * inv);
            __half2 S2 = dot128_h16(r_h[prv], e2h);
            r_h[cur][j] = __low2half(__hmul2(S2, g2));
            __syncthreads();
        }
        g_af[bc * N_ + j] = __half2float(r_h[m & 1][j]);
        if (j == 0) g_kf[bc] = kacc;
    } else {
        // ---------------- BACKWARD: nb = len-1-m steps ----------------
        // State pre-multiplied: bt[tau][i] = beta_tau_i * em_tau_i.
        __half2 e2h[64];   // (E[j,2q], E[j,2q+1]) : row j of E (contiguous)
        {
            const float2* tb2 = reinterpret_cast<const float2*>(
                trans + (size_t)c * N_ * N_ + (size_t)j * N_);
#pragma unroll
            for (int q = 0; q < 64; ++q) {
                float2 w = tb2[q];
                e2h[q] = __floats2half2_rn(__expf(w.x), __expf(w.y));
            }
        }
        const int tau0 = len - 1;
        const int nb   = len - 1 - m;
        r_h[0][j] = __float2half_rn(__expf(end_t[c * N_ + j] +
                                           ebase[(size_t)tau0 * estride]));
        __syncthreads();
#pragma unroll
        for (int s0 = 0; s0 < 8; ++s0) {
            int tt = tau0 - 1 - s0; tt = (tt < 0) ? 0 : tt;
            ering[s0] = __ldg(ebase + (size_t)tt * estride);
        }
        int s = 0;
#pragma unroll 1
        for (; s + 7 < nb; s += 8) {
#pragma unroll
            for (int u = 0; u < 8; ++u) {
                const int prv = u & 1;      // s is a multiple of 8
                const int cur = prv ^ 1;
                unsigned short ub = __half_as_ushort(r_h[prv][0]);
                int   ke  = (ub >> 10) & 0x1f;
                float inv = __int_as_float((131 - ke) << 23);
                kacc += ke;
                float em = __expf(ering[(s + u) & 7]);      // emit_{tau0-1-(s+u)}
                int tt = tau0 - 9 - (s + u); tt = (tt < 0) ? 0 : tt;
                ering[(s + u) & 7] = __ldg(ebase + (size_t)tt * estride);
                __half2 g2 = __float2half2_rn(em * inv);
                __half2 S2 = dot128_h16(r_h[prv], e2h);
                r_h[cur][j] = __low2half(__hmul2(S2, g2));
                __syncthreads();
            }
        }
#pragma unroll 1
        for (; s < nb; ++s) {
            const int prv = s & 1;
            const int cur = prv ^ 1;
            unsigned short ub = __half_as_ushort(r_h[prv][0]);
            int   ke  = (ub >> 10) & 0x1f;
            float inv = __int_as_float((131 - ke) << 23);
            kacc += ke;
            float em = __expf(ering[s & 7]);
            int tt = tau0 - 9 - s; tt = (tt < 0) ? 0 : tt;
            ering[s & 7] = __ldg(ebase + (size_t)tt * estride);
            __half2 g2 = __float2half2_rn(em * inv);
            __half2 S2 = dot128_h16(r_h[prv], e2h);
            r_h[cur][j] = __low2half(__hmul2(S2, g2));
            __syncthreads();
        }
        g_bt[bc * N_ + j] = __half2float(r_h[nb & 1][j]);
        if (j == 0) g_kb[bc] = kacc;
    }
}

// logZ = (kf + kb - 4*(len-1))*ln2 + log( sum_j af_j * bt_j * e^{-emit_m_j} )
__global__ void __launch_bounds__(128, 1)
crf_reduce_kernel(const float* __restrict__ emissions,
                  const int*   __restrict__ lengths,
                  float*       __restrict__ out)
{
    const int j  = threadIdx.x;
    const int bc = blockIdx.x;
    const int b  = bc >> 1;
    const int c  = bc & 1;
    const int len = lengths[b];
    const int m   = (len - 1) >> 1;

    __shared__ float red_sh[4];
    float em_m = emissions[(((size_t)b * T_ + m) * C_ + c) * N_ + j];
    float v = g_af[bc * N_ + j] * g_bt[bc * N_ + j] * __expf(-em_m);
#pragma unroll
    for (int o = 16; o > 0; o >>= 1)
        v += __shfl_xor_sync(0xffffffffu, v, o);
    if ((j & 31) == 0) red_sh[j >> 5] = v;
    __syncthreads();
    if (j == 0) {
        float Sf = (red_sh[0] + red_sh[1]) + (red_sh[2] + red_sh[3]);
        float logK = (float)(g_kf[bc] + g_kb[bc] - 4 * (len - 1)) * 0.6931471805599453f;
        out[bc] = logK + logf(Sf);
    }
}

extern "C" void kernel_launch(void* const* d_in, const int* in_sizes, int n_in,
                              void* d_out, int out_size) {
    const float* emissions = nullptr;
    const int*   lengths   = nullptr;
    const float* trans     = nullptr;
    const float* start_t   = nullptr;
    const float* end_t     = nullptr;

    for (int i = 0; i < n_in; ++i) {
        int sz = in_sizes[i];
        if (sz == B_ * T_ * C_ * N_)      emissions = (const float*)d_in[i];
        else if (sz == B_)                lengths   = (const int*)d_in[i];
        else if (sz == C_ * N_ * N_)      trans     = (const float*)d_in[i];
    }
    if (n_in > 3 && in_sizes[3] == C_ * N_) start_t = (const float*)d_in[3];
    for (int i = 0; i < n_in; ++i) {
        if (in_sizes[i] == C_ * N_ && (const float*)d_in[i] != start_t)
            end_t = (const float*)d_in[i];
    }
    if (!start_t) {
        for (int i = 0; i < n_in; ++i)
            if (in_sizes[i] == C_ * N_) { start_t = (const float*)d_in[i]; break; }
        for (int i = 0; i < n_in; ++i)
            if (in_sizes[i] == C_ * N_ && (const float*)d_in[i] != start_t)
                end_t = (const float*)d_in[i];
    }

    float* out = (float*)d_out;
    crf_sched_kernel<<<1, 256>>>(lengths);
    crf_bidir_kernel<<<2 * B_ * C_, N_>>>(emissions, lengths, trans, start_t, end_t);
    crf_reduce_kernel<<<B_ * C_, N_>>>(emissions, lengths, out);
}